// round 12
// baseline (speedup 1.0000x reference)
#include <cuda_runtime.h>
#include <cuda_bf16.h>
#include <math.h>
#include <stdint.h>

#define NN 100000
#define NE 640000
#define IND 64
#define HH  128
#define NG  128

typedef unsigned long long u64;

// ---------------- scratch (static device globals) ----------------
__device__ float g_h [NN*HH];
__device__ float g_m [NN*HH];
__device__ float g_Wint[IND*HH];
__device__ float g_Wft[HH*HH];
__device__ float g_Uft[HH*HH];
__device__ float g_Wht[HH*HH];
__device__ float g_Uht[HH*HH];
__device__ float g_e  [NN];
__device__ int   g_bounds[NG+1];
// CSR scratch
__device__ int g_deg[NN];
__device__ int g_off[NN+1];
__device__ int g_csr[NE];
__device__ int g_bsum[128];

__device__ __forceinline__ float sigf(float z)   { return __fdividef(1.f, 1.f + __expf(-z)); }
__device__ __forceinline__ float tanhfast(float z){ return 1.f - __fdividef(2.f, __expf(2.f*z) + 1.f); }

// ---- packed fp32x2 helpers (FFMA2) ----
__device__ __forceinline__ u64 dup2(float a){
    u64 r; asm("mov.b64 %0, {%1, %1};" : "=l"(r) : "f"(a)); return r;
}
__device__ __forceinline__ void ffma2(u64& d, u64 a, u64 b){
    asm("fma.rn.f32x2 %0, %1, %2, %0;" : "+l"(d) : "l"(a), "l"(b));
}
__device__ __forceinline__ float2 unpk(u64 v){
    float2 r; asm("mov.b64 {%0, %1}, %2;" : "=f"(r.x), "=f"(r.y) : "l"(v)); return r;
}

// ---- cp.async helpers (sm_80 baseline PTX) ----
__device__ __forceinline__ void cpa16(uint32_t saddr, const void* g){
    asm volatile("cp.async.cg.shared.global [%0], [%1], 16;" :: "r"(saddr), "l"(g) : "memory");
}
#define CPA_COMMIT() asm volatile("cp.async.commit_group;" ::: "memory")
#define CPA_WAIT0()  asm volatile("cp.async.wait_group 0;" ::: "memory")

// ---------------- batched transpose of the 5 weight matrices ----------------
__global__ void k_prep5(const float* __restrict__ Win, const float* __restrict__ Wf,
                        const float* __restrict__ Uf,  const float* __restrict__ Wh,
                        const float* __restrict__ Uh){
    __shared__ float t[32][33];
    int mz = blockIdx.z;
    const float* src; float* dst; int R = 128, C = 128;
    switch (mz){
        case 0: src = Win; dst = g_Wint; C = 64; break;
        case 1: src = Wf;  dst = g_Wft; break;
        case 2: src = Uf;  dst = g_Uft; break;
        case 3: src = Wh;  dst = g_Wht; break;
        default: src = Uh; dst = g_Uht; break;
    }
    int c = blockIdx.x*32 + threadIdx.x;
    int r = blockIdx.y*32 + threadIdx.y;
    if (r < R && c < C) t[threadIdx.y][threadIdx.x] = src[r*C + c];
    __syncthreads();
    int rc = blockIdx.x*32 + threadIdx.y;
    int cc = blockIdx.y*32 + threadIdx.x;
    if (rc < C && cc < R) dst[rc*R + cc] = t[threadIdx.x][threadIdx.y];
}

// ---------------- bounds + zero deg ----------------
__global__ void k_bounds(const int* __restrict__ batch){
    int i = blockIdx.x*blockDim.x + threadIdx.x;
    if (i < NN) g_deg[i] = 0;
    if (i >= NN) return;
    int b = batch[i];
    if (i == 0)      { for (int g = 0;    g <= b;  g++) g_bounds[g] = 0; }
    else             { int pb = batch[i-1];
                       for (int g = pb+1; g <= b;  g++) g_bounds[g] = i; }
    if (i == NN-1)   { for (int g = b+1;  g <= NG; g++) g_bounds[g] = NN; }
}

// ---------------- CSR build ----------------
__global__ void k_hist(const int* __restrict__ dst){
    int e = blockIdx.x*blockDim.x + threadIdx.x;
    if (e < NE) atomicAdd(&g_deg[dst[e]], 1);
}
__global__ __launch_bounds__(1024) void k_scan1(){
    __shared__ int sd[1024];
    int t = threadIdx.x, i = blockIdx.x*1024 + t;
    int v = (i < NN) ? g_deg[i] : 0;
    sd[t] = v; __syncthreads();
#pragma unroll
    for (int o = 1; o < 1024; o <<= 1){
        int x = (t >= o) ? sd[t-o] : 0;
        __syncthreads();
        sd[t] += x;
        __syncthreads();
    }
    if (i < NN) g_off[i] = sd[t] - v;
    if (t == 1023) g_bsum[blockIdx.x] = sd[1023];
}
__global__ __launch_bounds__(128) void k_scan2(int nb){
    __shared__ int sd[128];
    int t = threadIdx.x;
    int v = (t < nb) ? g_bsum[t] : 0;
    sd[t] = v; __syncthreads();
#pragma unroll
    for (int o = 1; o < 128; o <<= 1){
        int x = (t >= o) ? sd[t-o] : 0;
        __syncthreads();
        sd[t] += x;
        __syncthreads();
    }
    if (t < nb) g_bsum[t] = sd[t] - v;
}
__global__ void k_scan3(){
    int i = blockIdx.x*blockDim.x + threadIdx.x;
    if (i < NN){ int o = g_off[i] + g_bsum[i >> 10]; g_off[i] = o; g_deg[i] = o; }
    if (i == 0) g_off[NN] = NE;
}
__global__ void k_fill(const int* __restrict__ src, const int* __restrict__ dst){
    int e = blockIdx.x*blockDim.x + threadIdx.x;
    if (e >= NE) return;
    int pos = atomicAdd(&g_deg[dst[e]], 1);
    g_csr[pos] = src[e];
}

// ---------------- aggregation: m[n] = sum_{e in csr[n]} h[src_e] (unroll-4) ----------------
__global__ __launch_bounds__(256) void k_agg(){
    int w = (blockIdx.x*blockDim.x + threadIdx.x) >> 5;
    if (w >= NN) return;
    int lane = threadIdx.x & 31;
    int s = __ldg(&g_off[w]), e = __ldg(&g_off[w+1]);
    const float4* h4 = (const float4*)g_h;
    float4 a0 = make_float4(0.f,0.f,0.f,0.f);
    float4 a1 = make_float4(0.f,0.f,0.f,0.f);
    float4 a2 = make_float4(0.f,0.f,0.f,0.f);
    float4 a3 = make_float4(0.f,0.f,0.f,0.f);
    int p = s;
    for (; p + 3 < e; p += 4){
        int s0 = __ldg(&g_csr[p]);
        int s1 = __ldg(&g_csr[p+1]);
        int s2 = __ldg(&g_csr[p+2]);
        int s3 = __ldg(&g_csr[p+3]);
        float4 v0 = __ldg(h4 + (size_t)s0*32 + lane);
        float4 v1 = __ldg(h4 + (size_t)s1*32 + lane);
        float4 v2 = __ldg(h4 + (size_t)s2*32 + lane);
        float4 v3 = __ldg(h4 + (size_t)s3*32 + lane);
        a0.x += v0.x; a0.y += v0.y; a0.z += v0.z; a0.w += v0.w;
        a1.x += v1.x; a1.y += v1.y; a1.z += v1.z; a1.w += v1.w;
        a2.x += v2.x; a2.y += v2.y; a2.z += v2.z; a2.w += v2.w;
        a3.x += v3.x; a3.y += v3.y; a3.z += v3.z; a3.w += v3.w;
    }
    for (; p < e; p++){
        int s0 = __ldg(&g_csr[p]);
        float4 v0 = __ldg(h4 + (size_t)s0*32 + lane);
        a0.x += v0.x; a0.y += v0.y; a0.z += v0.z; a0.w += v0.w;
    }
    a0.x += a1.x + a2.x + a3.x;
    a0.y += a1.y + a2.y + a3.y;
    a0.z += a1.z + a2.z + a3.z;
    a0.w += a1.w + a2.w + a3.w;
    ((float4*)g_m)[(size_t)w*32 + lane] = a0;
}

// ---------------- input layer (FFMA2) ----------------
__global__ __launch_bounds__(256) void k_input(const float* __restrict__ x,
                                               const float* __restrict__ bin){
    extern __shared__ float sm[];
    float4* Ws4 = (float4*)sm;
    float4* Xs4 = (float4*)(sm + IND*HH);
    int tid = threadIdx.x;
    int jt = tid & 31, nt = tid >> 5;

    const float4* Wg = (const float4*)g_Wint;
#pragma unroll
    for (int i = 0; i < 8; i++) Ws4[tid + i*256] = Wg[tid + i*256];

    int base = blockIdx.x * 64;
    const float4* Xg = (const float4*)x;
#pragma unroll
    for (int i = 0; i < 4; i++){
        int q = tid + i*256;
        int rn = q >> 4, col = q & 15;
        int gn = base + rn;
        Xs4[q] = (gn < NN) ? Xg[gn*16 + col] : make_float4(0.f,0.f,0.f,0.f);
    }
    __syncthreads();

    u64 acc[8][2];
#pragma unroll
    for (int i = 0; i < 8; i++){ acc[i][0] = 0ull; acc[i][1] = 0ull; }

    for (int k = 0; k < IND; k += 4){
        float a[8][4];
#pragma unroll
        for (int i = 0; i < 8; i++){
            float4 t4 = Xs4[(nt*8+i)*16 + (k>>2)];
            a[i][0]=t4.x; a[i][1]=t4.y; a[i][2]=t4.z; a[i][3]=t4.w;
        }
#pragma unroll
        for (int kk = 0; kk < 4; kk++){
            ulonglong2 wv = ((const ulonglong2*)Ws4)[(k+kk)*32 + jt];
#pragma unroll
            for (int i = 0; i < 8; i++){
                u64 a2 = dup2(a[i][kk]);
                ffma2(acc[i][0], a2, wv.x);
                ffma2(acc[i][1], a2, wv.y);
            }
        }
    }
    float4 bb = ((const float4*)bin)[jt];
#pragma unroll
    for (int i = 0; i < 8; i++){
        int n = base + nt*8 + i;
        if (n < NN){
            float2 z01 = unpk(acc[i][0]);
            float2 z23 = unpk(acc[i][1]);
            float4 o;
            o.x = fmaxf(z01.x+bb.x, 0.f);
            o.y = fmaxf(z01.y+bb.y, 0.f);
            o.z = fmaxf(z23.x+bb.z, 0.f);
            o.w = fmaxf(z23.y+bb.w, 0.f);
            ((float4*)g_h)[n*32 + jt] = o;
        }
    }
}

// ---------------- fused MGU step with cp.async weight swaps ----------------
#define SMF ((2*HH*HH + 3*64*HH) * 4)

__device__ __forceinline__ void mgu_gemm(const float4* __restrict__ As4,
    const float4* __restrict__ Bs4, const float4* __restrict__ Ws4,
    const float4* __restrict__ Us4, int nt, int jt, u64 acc[8][2])
{
#pragma unroll
    for (int i = 0; i < 8; i++){ acc[i][0] = 0ull; acc[i][1] = 0ull; }
    for (int k = 0; k < HH; k += 4){
        float a[8][4], b[8][4];
#pragma unroll
        for (int i = 0; i < 8; i++){
            float4 ta = As4[(nt*8+i)*32 + (k>>2)];
            float4 tb = Bs4[(nt*8+i)*32 + (k>>2)];
            a[i][0]=ta.x; a[i][1]=ta.y; a[i][2]=ta.z; a[i][3]=ta.w;
            b[i][0]=tb.x; b[i][1]=tb.y; b[i][2]=tb.z; b[i][3]=tb.w;
        }
#pragma unroll
        for (int kk = 0; kk < 4; kk++){
            ulonglong2 wv = ((const ulonglong2*)Ws4)[(k+kk)*32 + jt];
            ulonglong2 uv = ((const ulonglong2*)Us4)[(k+kk)*32 + jt];
#pragma unroll
            for (int i = 0; i < 8; i++){
                u64 a2 = dup2(a[i][kk]);
                u64 b2 = dup2(b[i][kk]);
                ffma2(acc[i][0], a2, wv.x);
                ffma2(acc[i][1], a2, wv.y);
                ffma2(acc[i][0], b2, uv.x);
                ffma2(acc[i][1], b2, uv.y);
            }
        }
    }
}

__global__ __launch_bounds__(256, 1) void k_mgu(
    const float* __restrict__ A, float* __restrict__ H,
    const float* __restrict__ bfp, const float* __restrict__ bhp)
{
    extern __shared__ float sm[];
    float4* Ws4 = (float4*)sm;                          // phase weights W (4096 f4)
    float4* Us4 = (float4*)(sm + HH*HH);                // phase weights U (4096 f4)
    float4* As4 = (float4*)(sm + 2*HH*HH);              // m tile
    float4* Hs4 = (float4*)(sm + 2*HH*HH + 64*HH);      // h tile
    float4* Gs4 = (float4*)(sm + 2*HH*HH + 2*64*HH);    // g tile
    int tid = threadIdx.x;
    int jt = tid & 31, nt = tid >> 5;

    uint32_t wsa = (uint32_t)__cvta_generic_to_shared(Ws4);
    uint32_t usa = (uint32_t)__cvta_generic_to_shared(Us4);

    float4 bf4 = ((const float4*)bfp)[jt];
    float4 bh4 = ((const float4*)bhp)[jt];
    const float4* Ag = (const float4*)A;
    const float4* Hg = (const float4*)H;
    const float4* Wfg = (const float4*)g_Wft;
    const float4* Ufg = (const float4*)g_Uft;
    const float4* Whg = (const float4*)g_Wht;
    const float4* Uhg = (const float4*)g_Uht;

    int ntiles = (NN + 63) >> 6;

    float4 pa[8], pb[8];
    {
        int base = blockIdx.x << 6;
#pragma unroll
        for (int i = 0; i < 8; i++){
            int gn = base + nt + i*8;   // matches store index tid + i*256
            if (gn < NN){ pa[i] = __ldg(Ag + (size_t)gn*32 + jt); pb[i] = __ldg(Hg + (size_t)gn*32 + jt); }
            else        { float4 z = make_float4(0.f,0.f,0.f,0.f); pa[i] = z; pb[i] = z; }
        }
    }

    for (int tile = blockIdx.x; tile < ntiles; tile += gridDim.x){
        int base = tile << 6;
        __syncthreads();   // prior tile's smem reads complete
#pragma unroll
        for (int i = 0; i < 8; i++){
            As4[tid + i*256] = pa[i];
            Hs4[tid + i*256] = pb[i];
        }
        // async phase-1 weight copies (no reg staging)
#pragma unroll
        for (int i = 0; i < 16; i++){
            int q = tid + i*256;
            cpa16(wsa + q*16, Wfg + q);
            cpa16(usa + q*16, Ufg + q);
        }
        CPA_COMMIT();

        // prefetch next tile into regs while copies fly
        int ntile = tile + gridDim.x;
        if (ntile < ntiles){
            int nb = ntile << 6;
#pragma unroll
            for (int i = 0; i < 8; i++){
                int gn = nb + nt + i*8;
                if (gn < NN){ pa[i] = __ldg(Ag + (size_t)gn*32 + jt); pb[i] = __ldg(Hg + (size_t)gn*32 + jt); }
                else        { float4 z = make_float4(0.f,0.f,0.f,0.f); pa[i] = z; pb[i] = z; }
            }
        }

        CPA_WAIT0();
        __syncthreads();

        u64 acc[8][2];
        mgu_gemm(As4, Hs4, Ws4, Us4, nt, jt, acc);
        __syncthreads();   // all warps done reading phase-1 weights

        // issue phase-2 weight copies, overlap with epilogue-1 compute
#pragma unroll
        for (int i = 0; i < 16; i++){
            int q = tid + i*256;
            cpa16(wsa + q*16, Whg + q);
            cpa16(usa + q*16, Uhg + q);
        }
        CPA_COMMIT();

        // f = sigmoid(z1), g = f*h -> Gs4 ; keep f in regs
        float f[8][4];
#pragma unroll
        for (int i = 0; i < 8; i++){
            float2 z01 = unpk(acc[i][0]);
            float2 z23 = unpk(acc[i][1]);
            f[i][0] = sigf(z01.x + bf4.x);
            f[i][1] = sigf(z01.y + bf4.y);
            f[i][2] = sigf(z23.x + bf4.z);
            f[i][3] = sigf(z23.y + bf4.w);
            float4 hv = Hs4[(nt*8+i)*32 + jt];
            Gs4[(nt*8+i)*32 + jt] = make_float4(f[i][0]*hv.x, f[i][1]*hv.y, f[i][2]*hv.z, f[i][3]*hv.w);
        }

        CPA_WAIT0();
        __syncthreads();   // g complete + phase-2 weights landed

        mgu_gemm(As4, Gs4, Ws4, Us4, nt, jt, acc);

        // h_new = (1-f)*h + f*tanh(z2)
#pragma unroll
        for (int i = 0; i < 8; i++){
            int n = base + nt*8 + i;
            if (n < NN){
                float2 z01 = unpk(acc[i][0]);
                float2 z23 = unpk(acc[i][1]);
                float t0 = tanhfast(z01.x + bh4.x);
                float t1 = tanhfast(z01.y + bh4.y);
                float t2 = tanhfast(z23.x + bh4.z);
                float t3 = tanhfast(z23.y + bh4.w);
                float4 hv = Hs4[(nt*8+i)*32 + jt];
                float4 o;
                o.x = (1.f-f[i][0])*hv.x + f[i][0]*t0;
                o.y = (1.f-f[i][1])*hv.y + f[i][1]*t1;
                o.z = (1.f-f[i][2])*hv.z + f[i][2]*t2;
                o.w = (1.f-f[i][3])*hv.w + f[i][3]*t3;
                ((float4*)H)[(size_t)n*32 + jt] = o;
            }
        }
    }
}

// ---------------- fused Set2Set (3 steps LSTM+attn) + prediction ----------------
__global__ __launch_bounds__(256) void k_s2s(
    const float* __restrict__ wih, const float* __restrict__ whh,
    const float* __restrict__ bih, const float* __restrict__ bhh,
    const float* __restrict__ wp,  const float* __restrict__ bp,
    float* __restrict__ out)
{
    __shared__ __align__(16) float qs[2*HH];
    __shared__ __align__(16) float hl[HH];
    __shared__ __align__(16) float cl[HH];
    __shared__ float gt[4*HH];
    __shared__ float red[8];
    __shared__ __align__(16) float rp[8][HH];

    int g = blockIdx.x, t = threadIdx.x, wid = t >> 5, lane = t & 31;
    int s = g_bounds[g], e = g_bounds[g+1];
    const float4* h4 = (const float4*)g_h;

    if (t < HH){ hl[t] = 0.f; cl[t] = 0.f; }
    qs[t] = 0.f;
    __syncthreads();

    for (int step = 0; step < 3; step++){
        {
            const float4* qs4 = (const float4*)qs;
            const float4* hl4 = (const float4*)hl;
            float4 q0 = qs4[lane], q1 = qs4[32 + lane];
            float4 hh0 = hl4[lane];
            for (int r = wid*64; r < wid*64 + 64; r++){
                const float4* wr = (const float4*)(wih + (size_t)r*2*HH);
                const float4* hr = (const float4*)(whh + (size_t)r*HH);
                float4 w0 = __ldg(wr + lane);
                float4 w1 = __ldg(wr + 32 + lane);
                float4 h0 = __ldg(hr + lane);
                float p = w0.x*q0.x + w0.y*q0.y + w0.z*q0.z + w0.w*q0.w
                        + w1.x*q1.x + w1.y*q1.y + w1.z*q1.z + w1.w*q1.w
                        + h0.x*hh0.x + h0.y*hh0.y + h0.z*hh0.z + h0.w*hh0.w;
#pragma unroll
                for (int o = 16; o; o >>= 1) p += __shfl_xor_sync(0xffffffffu, p, o);
                if (lane == 0) gt[r] = p + __ldg(&bih[r]) + __ldg(&bhh[r]);
            }
        }
        __syncthreads();
        if (t < HH){
            float c = sigf(gt[HH+t])*cl[t] + sigf(gt[t])*tanhfast(gt[2*HH+t]);
            cl[t] = c;
            float hv = sigf(gt[3*HH+t])*tanhfast(c);
            hl[t] = hv;
            qs[t] = hv;
        }
        __syncthreads();

        float4 q4 = ((const float4*)hl)[lane];
        float lmax = -3.4e38f;
        for (int b = s + wid*4; b < e; b += 32){
            float p[4];
#pragma unroll
            for (int j = 0; j < 4; j++){
                if (b + j < e){
                    float4 x = __ldg(h4 + (size_t)(b+j)*32 + lane);
                    p[j] = x.x*q4.x + x.y*q4.y + x.z*q4.z + x.w*q4.w;
                } else p[j] = 0.f;
            }
#pragma unroll
            for (int o = 16; o; o >>= 1){
#pragma unroll
                for (int j = 0; j < 4; j++) p[j] += __shfl_xor_sync(0xffffffffu, p[j], o);
            }
#pragma unroll
            for (int j = 0; j < 4; j++){
                if (b + j < e){
                    if (lane == 0) g_e[b+j] = p[j];
                    lmax = fmaxf(lmax, p[j]);
                }
            }
        }
        if (lane == 0) red[wid] = lmax;
        __syncthreads();
        float emax = -3.4e38f;
#pragma unroll
        for (int w = 0; w < 8; w++) emax = fmaxf(emax, red[w]);
        __syncthreads();

        float lsum = 0.f;
        for (int n = s + t; n < e; n += 256){
            float w = __expf(g_e[n] - emax);
            g_e[n] = w;
            lsum += w;
        }
#pragma unroll
        for (int o = 16; o; o >>= 1) lsum += __shfl_xor_sync(0xffffffffu, lsum, o);
        if (lane == 0) red[wid] = lsum;
        __syncthreads();
        float denom = 0.f;
#pragma unroll
        for (int w = 0; w < 8; w++) denom += red[w];

        float4 racc = make_float4(0.f,0.f,0.f,0.f);
        for (int b = s + wid*4; b < e; b += 32){
#pragma unroll
            for (int j = 0; j < 4; j++){
                if (b + j < e){
                    float coef = __ldg(&g_e[b+j]);
                    float4 x = __ldg(h4 + (size_t)(b+j)*32 + lane);
                    racc.x += coef*x.x; racc.y += coef*x.y;
                    racc.z += coef*x.z; racc.w += coef*x.w;
                }
            }
        }
        ((float4*)rp[wid])[lane] = racc;
        __syncthreads();
        if (t < HH){
            float r = 0.f;
#pragma unroll
            for (int w = 0; w < 8; w++) r += rp[w][t];
            qs[HH + t] = (e > s) ? (r / denom) : 0.f;
        }
        __syncthreads();
    }

    float p = qs[t] * __ldg(&wp[t]);
#pragma unroll
    for (int o = 16; o; o >>= 1) p += __shfl_xor_sync(0xffffffffu, p, o);
    if (lane == 0) red[wid] = p;
    __syncthreads();
    if (t == 0){
        float r = 0.f;
#pragma unroll
        for (int w = 0; w < 8; w++) r += red[w];
        out[g] = r + __ldg(&bp[0]);
    }
}

// ---------------- launcher ----------------
extern "C" void kernel_launch(void* const* d_in, const int* in_sizes, int n_in,
                              void* d_out, int out_size){
    const float* x    = (const float*)d_in[0];
    const int*   ei   = (const int*)  d_in[1];
    const int*   batch= (const int*)  d_in[2];
    const float* Win  = (const float*)d_in[3];
    const float* bin  = (const float*)d_in[4];
    const float* Wf   = (const float*)d_in[5];
    const float* Uf   = (const float*)d_in[6];
    const float* bf   = (const float*)d_in[7];
    const float* Wh   = (const float*)d_in[8];
    const float* Uh   = (const float*)d_in[9];
    const float* bh   = (const float*)d_in[10];
    const float* wih  = (const float*)d_in[11];
    const float* whh  = (const float*)d_in[12];
    const float* bih  = (const float*)d_in[13];
    const float* bhh  = (const float*)d_in[14];
    const float* wp   = (const float*)d_in[15];
    const float* bp   = (const float*)d_in[16];
    float* out = (float*)d_out;

    float *p_m, *p_h;
    cudaGetSymbolAddress((void**)&p_m, g_m);
    cudaGetSymbolAddress((void**)&p_h, g_h);

    cudaFuncSetAttribute(k_mgu,   cudaFuncAttributeMaxDynamicSharedMemorySize, SMF);
    cudaFuncSetAttribute(k_input, cudaFuncAttributeMaxDynamicSharedMemorySize, 49152);

    const int* esrc = ei;
    const int* edst = ei + NE;
    const int NB1K = (NN + 1023) / 1024;

    k_prep5<<<dim3(4,4,5), dim3(32,32)>>>(Win, Wf, Uf, Wh, Uh);
    k_bounds<<<(NN+255)/256, 256>>>(batch);

    k_hist<<<(NE+255)/256, 256>>>(edst);
    k_scan1<<<NB1K, 1024>>>();
    k_scan2<<<1, 128>>>(NB1K);
    k_scan3<<<(NN+255)/256, 256>>>();
    k_fill<<<(NE+255)/256, 256>>>(esrc, edst);

    k_input<<<(NN+63)/64, 256, 49152>>>(x, bin);

    for (int step = 0; step < 3; step++){
        k_agg<<<(NN*32 + 255)/256, 256>>>();
        k_mgu<<<152, 256, SMF>>>(p_m, p_h, bf, bh);
    }

    k_s2s<<<NG, 256>>>(wih, whh, bih, bhh, wp, bp, out);
}